// round 11
// baseline (speedup 1.0000x reference)
#include <cuda_runtime.h>

#define NB    8
#define NH    16
#define HDIM  64
#define NDIMS 1024
#define CTXL  4096

// Block-role layout: all blocks wave-1 resident (444 = 148 SMs x occ 3).
#define N_QKV  192
#define N_ATTN 128
#define N_PROJ 64
#define N_FILL 60
#define GRID_TOTAL (N_QKV + N_ATTN + N_PROJ + N_FILL)   // 444
#define N_FILLW (N_QKV + N_FILL)                        // 252 fill workers

// Scratch (__device__ globals: allocation-free rule)
__device__ __align__(16) float g_q [128 * 1024];
__device__ __align__(16) float g_k [128 * 1024];
__device__ __align__(16) float g_v [128 * 1024];
__device__ __align__(16) float g_A1[128 * 1024];
__device__ __align__(16) float g_A2[128 * 1024];
__device__ float g_diffpart[128];
__device__ int   g_qkv_flag[64];     // [rt*16+ct], counts to 3
__device__ int   g_attn_done;        // counts to 128
__device__ int   g_proj_passed;      // counts to 64, self-resets

// ---------------------------------------------------------------------------
// tf32 helpers
// ---------------------------------------------------------------------------
__device__ __forceinline__ unsigned f2tf(float f) {
    unsigned r;
    asm("cvt.rna.tf32.f32 %0, %1;" : "=r"(r) : "f"(f));
    return r;
}
__device__ __forceinline__ float f2tf_f(float f) {
    return __uint_as_float(f2tf(f));
}
__device__ __forceinline__ void mma_tf32(float* c, unsigned a0, unsigned a1,
                                         unsigned a2, unsigned a3,
                                         unsigned b0, unsigned b1) {
    asm("mma.sync.aligned.m16n8k8.row.col.f32.tf32.tf32.f32 "
        "{%0,%1,%2,%3},{%4,%5,%6,%7},{%8,%9},{%0,%1,%2,%3};"
        : "+f"(c[0]), "+f"(c[1]), "+f"(c[2]), "+f"(c[3])
        : "r"(a0), "r"(a1), "r"(a2), "r"(a3), "r"(b0), "r"(b1));
}

// ---------------------------------------------------------------------------
// Fill share for one of N_FILLW workers: write ob to all rows s>=16.
// Rows s<16 are written by proj blocks (disjoint; no ordering needed).
// ---------------------------------------------------------------------------
__device__ __forceinline__ void fill_share(int worker, int t,
                                           float4* __restrict__ out4,
                                           const float4* __restrict__ ob4) {
    const float4 v = ob4[t];                  // i mod 256 == t -> column
    const unsigned stride = (unsigned)N_FILLW * 256u;
    for (unsigned i = (unsigned)worker * 256u + t; i < 8388608u; i += stride)
        if ((i & 1048575u) >= 4096u)          // skip s<16 of each batch
            out4[i] = v;
}

// ---------------------------------------------------------------------------
// Mega kernel: fused-LN qkv GEMM + attention + projection + fill, one launch.
// ---------------------------------------------------------------------------
__global__ void __launch_bounds__(256, 3) mega_kernel(
    const float* __restrict__ x,
    const float* __restrict__ qw, const float* __restrict__ qb,
    const float* __restrict__ kw,
    const float* __restrict__ vw, const float* __restrict__ vb,
    const float* __restrict__ ow, const float* __restrict__ ob,
    const float* __restrict__ lna, const float* __restrict__ lnb,
    const float* __restrict__ lnc, const float* __restrict__ lnd,
    const float* __restrict__ lqw, const float* __restrict__ lqb,
    const float* __restrict__ lkw, const float* __restrict__ lkb,
    const float* __restrict__ lvw, const float* __restrict__ lvb,
    float* __restrict__ out)
{
    extern __shared__ float sm[];
    const int t = threadIdx.x;
    const int bid = blockIdx.x;

    // =====================================================================
    // ROLE 1: fused LN + q/k/v GEMM (bids 0..191), then become fill worker.
    // =====================================================================
    if (bid < N_QKV) {
        const int mat = bid >> 6;
        const int sub = bid & 63;
        const int rt = sub >> 4, ct = sub & 15;
        const int r0 = rt * 32, c0 = ct * 64;
        const float* W    = (mat == 0) ? qw : (mat == 1) ? kw : vw;
        const float* lnw  = (mat == 0) ? lna : lnb;
        const float* bias = (mat == 0) ? qb : (mat == 2) ? vb : (const float*)0;
        float* OUT        = (mat == 0) ? g_q : (mat == 1) ? g_k : g_v;

        float (*As)[68] = (float(*)[68])sm;           // 32 x 68 (tf32 bits)
        float (*Ws)[68] = As + 32;                    // 64 x 68 (tf32 bits)
        float* m_s = (float*)(Ws + 64);               // 32
        float* r_s = m_s + 32;                        // 32

        // ---- LN stats for this tile's 32 rows (8 threads per row) ----
        const int lr = t >> 3, sg = t & 7;
        const int grow = r0 + lr;
        const float* xrow = x + ((size_t)(grow >> 4) * CTXL + (grow & 15)) * NDIMS;
        {
            float sum = 0.f, sq = 0.f;
            const float4* x4 = (const float4*)xrow;
            for (int j = sg; j < 256; j += 8) {
                float4 vv = x4[j];
                sum += vv.x + vv.y + vv.z + vv.w;
                sq  += vv.x*vv.x + vv.y*vv.y + vv.z*vv.z + vv.w*vv.w;
            }
            #pragma unroll
            for (int o = 4; o; o >>= 1) {
                sum += __shfl_xor_sync(0xffffffffu, sum, o);
                sq  += __shfl_xor_sync(0xffffffffu, sq,  o);
            }
            if (sg == 0) {
                float m = sum * (1.f / 1024.f);
                float var = sq * (1.f / 1024.f) - m * m;
                m_s[lr] = m; r_s[lr] = rsqrtf(var + 1e-5f);
            }
        }
        __syncthreads();
        const float mm = m_s[lr], rs = r_s[lr];

        // ---- GEMM (tf32 conversion done at staging time) ----
        const int w = t >> 5, l = t & 31;
        const int mr  = (w >> 2) * 16;
        const int nc_ = (w & 3) * 16;
        const int g   = l >> 2, tig = l & 3;
        const int lk8 = sg * 8;

        const float* xp  = xrow + lk8;
        const float* Wp0 = W + (size_t)(c0 + lr) * 1024 + lk8;
        const float* Wp1 = W + (size_t)(c0 + 32 + lr) * 1024 + lk8;
        const float* lp  = lnw + lk8;

        float4 px0 = *(const float4*)xp,  px1 = *(const float4*)(xp + 4);
        float4 pl0 = *(const float4*)lp,  pl1 = *(const float4*)(lp + 4);
        float4 pw0 = *(const float4*)Wp0, pw1 = *(const float4*)(Wp0 + 4);
        float4 pw2 = *(const float4*)Wp1, pw3 = *(const float4*)(Wp1 + 4);

        float acc[2][4] = {{0,0,0,0},{0,0,0,0}};

        for (int k0 = 0; k0 < 1024; k0 += 64) {
            __syncthreads();
            {
                float4 a0, a1, b0, b1, b2, b3;
                a0.x = f2tf_f((px0.x - mm) * rs * pl0.x);
                a0.y = f2tf_f((px0.y - mm) * rs * pl0.y);
                a0.z = f2tf_f((px0.z - mm) * rs * pl0.z);
                a0.w = f2tf_f((px0.w - mm) * rs * pl0.w);
                a1.x = f2tf_f((px1.x - mm) * rs * pl1.x);
                a1.y = f2tf_f((px1.y - mm) * rs * pl1.y);
                a1.z = f2tf_f((px1.z - mm) * rs * pl1.z);
                a1.w = f2tf_f((px1.w - mm) * rs * pl1.w);
                b0.x = f2tf_f(pw0.x); b0.y = f2tf_f(pw0.y);
                b0.z = f2tf_f(pw0.z); b0.w = f2tf_f(pw0.w);
                b1.x = f2tf_f(pw1.x); b1.y = f2tf_f(pw1.y);
                b1.z = f2tf_f(pw1.z); b1.w = f2tf_f(pw1.w);
                b2.x = f2tf_f(pw2.x); b2.y = f2tf_f(pw2.y);
                b2.z = f2tf_f(pw2.z); b2.w = f2tf_f(pw2.w);
                b3.x = f2tf_f(pw3.x); b3.y = f2tf_f(pw3.y);
                b3.z = f2tf_f(pw3.z); b3.w = f2tf_f(pw3.w);
                *(float4*)&As[lr][lk8]          = a0; *(float4*)&As[lr][lk8 + 4]      = a1;
                *(float4*)&Ws[lr][lk8]          = b0; *(float4*)&Ws[lr][lk8 + 4]      = b1;
                *(float4*)&Ws[lr + 32][lk8]     = b2; *(float4*)&Ws[lr + 32][lk8 + 4] = b3;
            }
            __syncthreads();
            if (k0 + 64 < 1024) {
                px0 = *(const float4*)(xp  + k0 + 64); px1 = *(const float4*)(xp  + k0 + 68);
                pl0 = *(const float4*)(lp  + k0 + 64); pl1 = *(const float4*)(lp  + k0 + 68);
                pw0 = *(const float4*)(Wp0 + k0 + 64); pw1 = *(const float4*)(Wp0 + k0 + 68);
                pw2 = *(const float4*)(Wp1 + k0 + 64); pw3 = *(const float4*)(Wp1 + k0 + 68);
            }
            #pragma unroll
            for (int ks = 0; ks < 8; ks++) {
                const int kb = ks * 8;
                unsigned a0 = __float_as_uint(As[mr + g][kb + tig]);
                unsigned a1 = __float_as_uint(As[mr + g + 8][kb + tig]);
                unsigned a2 = __float_as_uint(As[mr + g][kb + tig + 4]);
                unsigned a3 = __float_as_uint(As[mr + g + 8][kb + tig + 4]);
                #pragma unroll
                for (int j = 0; j < 2; j++) {
                    unsigned b0 = __float_as_uint(Ws[nc_ + j * 8 + g][kb + tig]);
                    unsigned b1 = __float_as_uint(Ws[nc_ + j * 8 + g][kb + tig + 4]);
                    mma_tf32(acc[j], a0, a1, a2, a3, b0, b1);
                }
            }
        }
        const int row0 = r0 + mr + g, row1 = row0 + 8;
        #pragma unroll
        for (int j = 0; j < 2; j++) {
            const int colb = c0 + nc_ + j * 8 + 2 * tig;
            float b0v = 0.f, b1v = 0.f;
            if (bias) { b0v = bias[colb]; b1v = bias[colb + 1]; }
            OUT[(size_t)row0 * 1024 + colb]     = acc[j][0] + b0v;
            OUT[(size_t)row0 * 1024 + colb + 1] = acc[j][1] + b1v;
            OUT[(size_t)row1 * 1024 + colb]     = acc[j][2] + b0v;
            OUT[(size_t)row1 * 1024 + colb + 1] = acc[j][3] + b1v;
        }
        __threadfence();
        __syncthreads();
        if (t == 0) atomicAdd(&g_qkv_flag[rt * 16 + ct], 1);

        // ---- become fill worker (after releasing the flag) ----
        fill_share(bid, t, (float4*)out, (const float4*)ob);
        return;
    }

    // =====================================================================
    // ROLE 2: attention per (b,h) (bids 192..319). Spins on its 3 qkv flags.
    // =====================================================================
    if (bid < N_QKV + N_ATTN) {
        const int aidx = bid - N_QKV;
        const int b = aidx >> 4, h = aidx & 15;

        float (*w1)[65] = (float(*)[65])sm;          // wk, later wq (64x65)
        float (*w2)[65] = w1 + 64;                   // wv
        float (*kt)[65] = w2 + 64;
        float (*vt)[65] = kt + 16;
        float (*kn)[65] = vt + 16;
        float (*vi)[65] = kn + 16;
        float (*qc)[65] = vi + 16;
        float (*qn)[65] = qc + 16;
        float* rm  = (float*)(qn + 16);
        float* rr  = rm + 16;
        float* red = rr + 16;

        const int w = t >> 5, lane = t & 31;

        // stage wk->w1, wv->w2 while (possibly) waiting on producers
        {
            const int rw = t >> 4, col = (t & 15) * 4;
            #pragma unroll
            for (int p = 0; p < 4; p++) {
                int row = p * 16 + rw;
                float4 c = *(const float4*)(lkw + row * 64 + col);
                w1[row][col] = c.x; w1[row][col+1] = c.y; w1[row][col+2] = c.z; w1[row][col+3] = c.w;
                float4 e = *(const float4*)(lvw + row * 64 + col);
                w2[row][col] = e.x; w2[row][col+1] = e.y; w2[row][col+2] = e.z; w2[row][col+3] = e.w;
            }
        }
        if (t == 0) {
            while (*(volatile int*)&g_qkv_flag[(b >> 1) * 16 + h] < 3) __nanosleep(64);
            __threadfence();
        }
        __syncthreads();

        const int d = t & 63, s0 = t >> 6;
        const size_t base = (size_t)(b * 16) * 1024 + h * 64;
        #pragma unroll
        for (int r = 0; r < 4; r++) {
            int s = s0 + 4 * r;
            qc[s][d] = g_q[base + (size_t)s * 1024 + d];
            kt[s][d] = g_k[base + (size_t)s * 1024 + d];
            vt[s][d] = g_v[base + (size_t)s * 1024 + d];
        }
        __syncthreads();

        // kn_pre = k @ lkw.T + lkb, vi = v @ lvw.T + lvb
        {
            float akn[4], avi[4];
            const float bk = lkb[d], bv = lvb[d];
            #pragma unroll
            for (int r = 0; r < 4; r++) { akn[r] = bk; avi[r] = bv; }
            for (int e = 0; e < 64; e++) {
                float wke = w1[d][e], wve = w2[d][e];
                #pragma unroll
                for (int r = 0; r < 4; r++) {
                    int s = s0 + 4 * r;
                    akn[r] += kt[s][e] * wke;
                    avi[r] += vt[s][e] * wve;
                }
            }
            #pragma unroll
            for (int r = 0; r < 4; r++) { int s = s0 + 4 * r; kn[s][d] = akn[r]; vi[s][d] = avi[r]; }
        }
        __syncthreads();
        {   // LN over 64-dim kn rows
            const int s = t >> 4, l16 = t & 15;
            float v0 = kn[s][l16], v1 = kn[s][l16+16], v2 = kn[s][l16+32], v3 = kn[s][l16+48];
            float sum = v0+v1+v2+v3, sq = v0*v0+v1*v1+v2*v2+v3*v3;
            #pragma unroll
            for (int o = 8; o; o >>= 1) {
                sum += __shfl_xor_sync(0xffffffffu, sum, o);
                sq  += __shfl_xor_sync(0xffffffffu, sq,  o);
            }
            if (l16 == 0) {
                float m = sum * (1.f/64.f), var = sq * (1.f/64.f) - m*m;
                rm[s] = m; rr[s] = rsqrtf(var + 1e-5f);
            }
        }
        __syncthreads();
        {
            const float lndd = lnd[d];
            #pragma unroll
            for (int r = 0; r < 4; r++) {
                int s = s0 + 4 * r;
                kn[s][d] = (kn[s][d] - rm[s]) * rr[s] * lndd;
            }
        }
        __syncthreads();
        // restage wq into w1 (wk no longer needed)
        {
            const int rw = t >> 4, col = (t & 15) * 4;
            #pragma unroll
            for (int p = 0; p < 4; p++) {
                int row = p * 16 + rw;
                float4 a = *(const float4*)(lqw + row * 64 + col);
                w1[row][col] = a.x; w1[row][col+1] = a.y; w1[row][col+2] = a.z; w1[row][col+3] = a.w;
            }
        }
        __syncthreads();

        // ---- sync-free iteration loop: warp w owns rows sA=2w, sB=2w+1 ----
        const int d0 = lane, d1 = lane + 32;
        const int sA = 2 * w, sB = sA + 1;
        const float lqb0 = lqb[d0], lqb1 = lqb[d1];
        const float lnc0 = lnc[d0], lnc1 = lnc[d1];
        const size_t baseA = base + (size_t)sA * 1024;
        const size_t baseB = base + (size_t)sB * 1024;

        float diffacc = 0.f;
        float ipA0 = 0.f, ipA1 = 0.f, ipB0 = 0.f, ipB1 = 0.f;

        #pragma unroll
        for (int it = 0; it < 3; it++) {
            float aA0 = lqb0, aA1 = lqb1, aB0 = lqb0, aB1 = lqb1;
            #pragma unroll 16
            for (int e = 0; e < 64; e++) {
                float ca = qc[sA][e], cb = qc[sB][e];
                float w0 = w1[d0][e], wv1 = w1[d1][e];
                aA0 += ca * w0; aA1 += ca * wv1;
                aB0 += cb * w0; aB1 += cb * wv1;
            }
            float sumA = aA0 + aA1, sqA = aA0*aA0 + aA1*aA1;
            float sumB = aB0 + aB1, sqB = aB0*aB0 + aB1*aB1;
            #pragma unroll
            for (int o = 16; o; o >>= 1) {
                sumA += __shfl_xor_sync(0xffffffffu, sumA, o);
                sqA  += __shfl_xor_sync(0xffffffffu, sqA,  o);
                sumB += __shfl_xor_sync(0xffffffffu, sumB, o);
                sqB  += __shfl_xor_sync(0xffffffffu, sqB,  o);
            }
            float mA = sumA * (1.f/64.f), rA = rsqrtf(sqA * (1.f/64.f) - mA*mA + 1e-5f);
            float mB = sumB * (1.f/64.f), rB = rsqrtf(sqB * (1.f/64.f) - mB*mB + 1e-5f);
            qn[sA][d0] = (aA0 - mA) * rA * lnc0; qn[sA][d1] = (aA1 - mA) * rA * lnc1;
            qn[sB][d0] = (aB0 - mB) * rB * lnc0; qn[sB][d1] = (aB1 - mB) * rB * lnc1;
            __syncwarp();

            const int srow = (lane < 16) ? sA : sB;
            const int u = lane & 15;
            float lg = 0.f;
            #pragma unroll 16
            for (int e = 0; e < 64; e++) lg += qn[srow][e] * kn[u][e];
            lg *= 0.125f;
            float mx = lg;
            #pragma unroll
            for (int o = 8; o; o >>= 1) mx = fmaxf(mx, __shfl_xor_sync(0xffffffffu, mx, o));
            float ex = expf(lg - mx);
            float se = ex;
            #pragma unroll
            for (int o = 8; o; o >>= 1) se += __shfl_xor_sync(0xffffffffu, se, o);
            float p = ex / se;

            float oA0 = 0.f, oA1 = 0.f, oB0 = 0.f, oB1 = 0.f;
            #pragma unroll
            for (int uu = 0; uu < 16; uu++) {
                float pA = __shfl_sync(0xffffffffu, p, uu);
                float pB = __shfl_sync(0xffffffffu, p, uu + 16);
                float v0 = vi[uu][d0], vvv = vi[uu][d1];
                oA0 += pA * v0; oA1 += pA * vvv;
                oB0 += pB * v0; oB1 += pB * vvv;
            }

            if (it == 0) {
                ipA0 = oA0; ipA1 = oA1; ipB0 = oB0; ipB1 = oB1;
                qc[sA][d0] += oA0; qc[sA][d1] += oA1;
                qc[sB][d0] += oB0; qc[sB][d1] += oB1;
            } else if (it == 1) {
                diffacc += fabsf(oA0 - ipA0) + fabsf(oA1 - ipA1)
                         + fabsf(oB0 - ipB0) + fabsf(oB1 - ipB1);
                qc[sA][d0] += oA0; qc[sA][d1] += oA1;
                qc[sB][d0] += oB0; qc[sB][d1] += oB1;
                g_A1[baseA + d0] = oA0; g_A1[baseA + d1] = oA1;
                g_A1[baseB + d0] = oB0; g_A1[baseB + d1] = oB1;
            } else {
                g_A2[baseA + d0] = oA0; g_A2[baseA + d1] = oA1;
                g_A2[baseB + d0] = oB0; g_A2[baseB + d1] = oB1;
            }
            __syncwarp();
        }

        // block reduce diff -> g_diffpart[aidx], then release attn_done
        #pragma unroll
        for (int o = 16; o; o >>= 1) diffacc += __shfl_xor_sync(0xffffffffu, diffacc, o);
        if (lane == 0) red[w] = diffacc;
        __syncthreads();
        if (t == 0) {
            float v = 0.f;
            #pragma unroll
            for (int i = 0; i < 8; i++) v += red[i];
            g_diffpart[aidx] = v;
        }
        __threadfence();
        __syncthreads();
        if (t == 0) atomicAdd(&g_attn_done, 1);
        return;
    }

    // =====================================================================
    // ROLE 3: output projection (bids 320..383). Spins until all attn done,
    // reduces diffpart deterministically, full-K tf32 GEMM, writes acc+ob.
    // Also self-resets the sync flags for the next graph replay.
    // =====================================================================
    if (bid < N_QKV + N_ATTN + N_PROJ) {
        const int pidx = bid - (N_QKV + N_ATTN);
        const int r0 = (pidx >> 4) * 32;
        const int c0 = (pidx & 15) * 64;

        if (t == 0) {
            while (*(volatile int*)&g_attn_done < 128) __nanosleep(128);
            __threadfence();
            // self-reset for next replay: safe because ALL attn blocks are done
            // (attn_done==128); attn_done cleared by the LAST proj block here.
            g_qkv_flag[pidx] = 0;
            int p = atomicAdd(&g_proj_passed, 1);
            if (p == N_PROJ - 1) { g_attn_done = 0; g_proj_passed = 0; }
        }
        __syncthreads();

        // deterministic diff reduction (identical order in every block)
        if (t < 32) {
            float v = 0.f;
            #pragma unroll
            for (int j = 0; j < 4; j++) v += g_diffpart[t + j * 32];
            #pragma unroll
            for (int o = 16; o; o >>= 1) v += __shfl_xor_sync(0xffffffffu, v, o);
            if (t == 0) sm[0] = v;
        }
        __syncthreads();
        const float total = sm[0];
        __syncthreads();
        const float diff = total * (1.0f / 33554432.0f);
        const float* IN = (diff < (0.01f + 0.1f * diff)) ? g_A1 : g_A2;

        float (*As)[68] = (float(*)[68])sm;
        float (*Ws)[68] = As + 32;

        const int w = t >> 5, l = t & 31;
        const int mr  = (w >> 2) * 16;
        const int nc_ = (w & 3) * 16;
        const int g   = l >> 2, tig = l & 3;
        const int lr  = t >> 3, lk8 = (t & 7) * 8;

        float acc[2][4] = {{0,0,0,0},{0,0,0,0}};

        const float* Ap  = IN + (size_t)(r0 + lr) * 1024 + lk8;
        const float* Wp0 = ow + (size_t)(c0 + lr) * 1024 + lk8;
        const float* Wp1 = ow + (size_t)(c0 + 32 + lr) * 1024 + lk8;
        float4 pa0 = *(const float4*)Ap,  pa1 = *(const float4*)(Ap + 4);
        float4 pw0 = *(const float4*)Wp0, pw1 = *(const float4*)(Wp0 + 4);
        float4 pw2 = *(const float4*)Wp1, pw3 = *(const float4*)(Wp1 + 4);

        for (int k0 = 0; k0 < 1024; k0 += 64) {
            __syncthreads();
            {
                float4 a0, a1, b0, b1, b2, b3;
                a0.x = f2tf_f(pa0.x); a0.y = f2tf_f(pa0.y);
                a0.z = f2tf_f(pa0.z); a0.w = f2tf_f(pa0.w);
                a1.x = f2tf_f(pa1.x); a1.y = f2tf_f(pa1.y);
                a1.z = f2tf_f(pa1.z); a1.w = f2tf_f(pa1.w);
                b0.x = f2tf_f(pw0.x); b0.y = f2tf_f(pw0.y);
                b0.z = f2tf_f(pw0.z); b0.w = f2tf_f(pw0.w);
                b1.x = f2tf_f(pw1.x); b1.y = f2tf_f(pw1.y);
                b1.z = f2tf_f(pw1.z); b1.w = f2tf_f(pw1.w);
                b2.x = f2tf_f(pw2.x); b2.y = f2tf_f(pw2.y);
                b2.z = f2tf_f(pw2.z); b2.w = f2tf_f(pw2.w);
                b3.x = f2tf_f(pw3.x); b3.y = f2tf_f(pw3.y);
                b3.z = f2tf_f(pw3.z); b3.w = f2tf_f(pw3.w);
                *(float4*)&As[lr][lk8]          = a0; *(float4*)&As[lr][lk8 + 4]      = a1;
                *(float4*)&Ws[lr][lk8]          = b0; *(float4*)&Ws[lr][lk8 + 4]      = b1;
                *(float4*)&Ws[lr + 32][lk8]     = b2; *(float4*)&Ws[lr + 32][lk8 + 4] = b3;
            }
            __syncthreads();
            if (k0 + 64 < 1024) {
                pa0 = *(const float4*)(Ap  + k0 + 64); pa1 = *(const float4*)(Ap  + k0 + 68);
                pw0 = *(const float4*)(Wp0 + k0 + 64); pw1 = *(const float4*)(Wp0 + k0 + 68);
                pw2 = *(const float4*)(Wp1 + k0 + 64); pw3 = *(const float4*)(Wp1 + k0 + 68);
            }
            #pragma unroll
            for (int ks = 0; ks < 8; ks++) {
                const int kb = ks * 8;
                unsigned a0 = __float_as_uint(As[mr + g][kb + tig]);
                unsigned a1 = __float_as_uint(As[mr + g + 8][kb + tig]);
                unsigned a2 = __float_as_uint(As[mr + g][kb + tig + 4]);
                unsigned a3 = __float_as_uint(As[mr + g + 8][kb + tig + 4]);
                #pragma unroll
                for (int j = 0; j < 2; j++) {
                    unsigned b0 = __float_as_uint(Ws[nc_ + j * 8 + g][kb + tig]);
                    unsigned b1 = __float_as_uint(Ws[nc_ + j * 8 + g][kb + tig + 4]);
                    mma_tf32(acc[j], a0, a1, a2, a3, b0, b1);
                }
            }
        }
        const int row0 = r0 + mr + g, row1 = row0 + 8;
        const size_t o0 = ((size_t)(row0 >> 4) * CTXL + (row0 & 15)) * 1024;
        const size_t o1 = ((size_t)(row1 >> 4) * CTXL + (row1 & 15)) * 1024;
        #pragma unroll
        for (int j = 0; j < 2; j++) {
            const int colb = c0 + nc_ + j * 8 + 2 * tig;
            const float b0v = ob[colb], b1v = ob[colb + 1];
            out[o0 + colb]     = acc[j][0] + b0v;
            out[o0 + colb + 1] = acc[j][1] + b1v;
            out[o1 + colb]     = acc[j][2] + b0v;
            out[o1 + colb + 1] = acc[j][3] + b1v;
        }
        return;
    }

    // =====================================================================
    // ROLE 4: dedicated fill workers (bids 384..443), storing from t=0.
    // =====================================================================
    {
        const int fb = bid - (N_QKV + N_ATTN + N_PROJ);
        fill_share(N_QKV + fb, t, (float4*)out, (const float4*)ob);
    }
}

// ---------------------------------------------------------------------------
extern "C" void kernel_launch(void* const* d_in, const int* in_sizes, int n_in,
                              void* d_out, int out_size) {
    const float* x   = (const float*)d_in[0];
    const float* qw  = (const float*)d_in[1];
    const float* qb  = (const float*)d_in[2];
    const float* kw  = (const float*)d_in[3];
    const float* vw  = (const float*)d_in[4];
    const float* vb  = (const float*)d_in[5];
    const float* ow  = (const float*)d_in[6];
    const float* ob  = (const float*)d_in[7];
    const float* lna = (const float*)d_in[8];
    const float* lnb = (const float*)d_in[9];
    const float* lnc = (const float*)d_in[10];
    const float* lnd = (const float*)d_in[11];
    const float* lqw = (const float*)d_in[12];
    const float* lqb = (const float*)d_in[13];
    const float* lkw = (const float*)d_in[14];
    const float* lkb = (const float*)d_in[15];
    const float* lvw = (const float*)d_in[16];
    const float* lvb = (const float*)d_in[17];
    float* out = (float*)d_out;

    // dynamic smem sized for the attn role: (2*64*65 + 6*16*65 + 40) floats
    const int smem = (2 * 64 * 65 + 6 * 16 * 65 + 40) * 4;   // 58400 B
    cudaFuncSetAttribute(mega_kernel, cudaFuncAttributeMaxDynamicSharedMemorySize,
                         smem);

    mega_kernel<<<GRID_TOTAL, 256, smem>>>(x, qw, qb, kw, vw, vb, ow, ob,
                                           lna, lnb, lnc, lnd,
                                           lqw, lqb, lkw, lkb, lvw, lvb, out);
}

// round 12
// speedup vs baseline: 1.6279x; 1.6279x over previous
#include <cuda_runtime.h>

#define NB    8
#define NH    16
#define HDIM  64
#define NDIMS 1024
#define CTXL  4096

// Block-role layout: all blocks wave-1 resident (444 = 148 SMs x occ 3).
#define N_QKV  192
#define N_ATTN 128
#define N_PROJ 64
#define N_FILL 60
#define GRID_TOTAL (N_QKV + N_ATTN + N_PROJ + N_FILL)   // 444
#define FILL_PARTICIPANTS (N_QKV + N_ATTN + N_FILL)     // 380
#define FILL_CHUNK  8192u                                // float4s per chunk
#define FILL_NCHUNK 1024u                                // 1024*8192 = 8388608

// Scratch (__device__ globals: allocation-free rule)
__device__ __align__(16) float g_q [128 * 1024];
__device__ __align__(16) float g_k [128 * 1024];
__device__ __align__(16) float g_v [128 * 1024];
__device__ __align__(16) float g_A1[128 * 1024];
__device__ __align__(16) float g_A2[128 * 1024];
__device__ float g_diffpart[128];
__device__ int      g_qkv_flag[64];   // [rt*16+ct], counts to 3
__device__ int      g_attn_done;      // counts to 128
__device__ int      g_proj_passed;    // counts to 64, self-resets
__device__ unsigned g_fill_next;      // fill chunk counter (work stealing)
__device__ int      g_fill_done;      // fill participants finished

// ---------------------------------------------------------------------------
// tf32 helpers
// ---------------------------------------------------------------------------
__device__ __forceinline__ unsigned f2tf(float f) {
    unsigned r;
    asm("cvt.rna.tf32.f32 %0, %1;" : "=r"(r) : "f"(f));
    return r;
}
__device__ __forceinline__ void mma_tf32(float* c, unsigned a0, unsigned a1,
                                         unsigned a2, unsigned a3,
                                         unsigned b0, unsigned b1) {
    asm("mma.sync.aligned.m16n8k8.row.col.f32.tf32.tf32.f32 "
        "{%0,%1,%2,%3},{%4,%5,%6,%7},{%8,%9},{%0,%1,%2,%3};"
        : "+f"(c[0]), "+f"(c[1]), "+f"(c[2]), "+f"(c[3])
        : "r"(a0), "r"(a1), "r"(a2), "r"(a3), "r"(b0), "r"(b1));
}

// ---------------------------------------------------------------------------
// Work-stealing fill: grab 128KB chunks off a global counter, write ob to all
// rows with s>=16 (rows s<16 are written by proj; disjoint). Deterministic
// output regardless of which block writes which chunk. Self-resets flags.
// smslot: one shared float usable as a broadcast slot (block-synced).
// ---------------------------------------------------------------------------
__device__ __forceinline__ void fill_steal(int t, float* smslot,
                                           float4* __restrict__ out4,
                                           const float4* __restrict__ ob4) {
    const float4 v = ob4[t];                  // i mod 256 == t -> column
    volatile unsigned* slot = (volatile unsigned*)smslot;
    for (;;) {
        __syncthreads();
        if (t == 0) *slot = atomicAdd(&g_fill_next, 1u);
        __syncthreads();
        const unsigned c = *slot;
        if (c >= FILL_NCHUNK) break;
        const unsigned base = c * FILL_CHUNK;
        #pragma unroll 4
        for (unsigned i = base + t; i < base + FILL_CHUNK; i += 256u)
            if ((i & 1048575u) >= 4096u)      // skip s<16 of each batch
                out4[i] = v;
    }
    if (t == 0) {
        int d = atomicAdd(&g_fill_done, 1);
        if (d == FILL_PARTICIPANTS - 1) { g_fill_next = 0u; g_fill_done = 0; }
    }
}

// ---------------------------------------------------------------------------
// Mega kernel: fused-LN qkv GEMM + attention + projection + fill, one launch.
// ---------------------------------------------------------------------------
__global__ void __launch_bounds__(256, 3) mega_kernel(
    const float* __restrict__ x,
    const float* __restrict__ qw, const float* __restrict__ qb,
    const float* __restrict__ kw,
    const float* __restrict__ vw, const float* __restrict__ vb,
    const float* __restrict__ ow, const float* __restrict__ ob,
    const float* __restrict__ lna, const float* __restrict__ lnb,
    const float* __restrict__ lnc, const float* __restrict__ lnd,
    const float* __restrict__ lqw, const float* __restrict__ lqb,
    const float* __restrict__ lkw, const float* __restrict__ lkb,
    const float* __restrict__ lvw, const float* __restrict__ lvb,
    float* __restrict__ out)
{
    extern __shared__ float sm[];
    const int t = threadIdx.x;
    const int bid = blockIdx.x;

    // =====================================================================
    // ROLE 1: fused LN + q/k/v GEMM (bids 0..191), then steal fill chunks.
    // =====================================================================
    if (bid < N_QKV) {
        const int mat = bid >> 6;
        const int sub = bid & 63;
        const int rt = sub >> 4, ct = sub & 15;
        const int r0 = rt * 32, c0 = ct * 64;
        const float* W    = (mat == 0) ? qw : (mat == 1) ? kw : vw;
        const float* lnw  = (mat == 0) ? lna : lnb;
        const float* bias = (mat == 0) ? qb : (mat == 2) ? vb : (const float*)0;
        float* OUT        = (mat == 0) ? g_q : (mat == 1) ? g_k : g_v;

        float (*As)[68] = (float(*)[68])sm;           // 32 x 68
        float (*Ws)[68] = As + 32;                    // 64 x 68
        float* m_s = (float*)(Ws + 64);               // 32
        float* r_s = m_s + 32;                        // 32

        // ---- LN stats for this tile's 32 rows (8 threads per row) ----
        const int lr = t >> 3, sg = t & 7;
        const int grow = r0 + lr;
        const float* xrow = x + ((size_t)(grow >> 4) * CTXL + (grow & 15)) * NDIMS;
        {
            float sum = 0.f, sq = 0.f;
            const float4* x4 = (const float4*)xrow;
            for (int j = sg; j < 256; j += 8) {
                float4 vv = x4[j];
                sum += vv.x + vv.y + vv.z + vv.w;
                sq  += vv.x*vv.x + vv.y*vv.y + vv.z*vv.z + vv.w*vv.w;
            }
            #pragma unroll
            for (int o = 4; o; o >>= 1) {
                sum += __shfl_xor_sync(0xffffffffu, sum, o);
                sq  += __shfl_xor_sync(0xffffffffu, sq,  o);
            }
            if (sg == 0) {
                float m = sum * (1.f / 1024.f);
                float var = sq * (1.f / 1024.f) - m * m;
                m_s[lr] = m; r_s[lr] = rsqrtf(var + 1e-5f);
            }
        }
        __syncthreads();
        const float mm = m_s[lr], rs = r_s[lr];

        // ---- GEMM ----
        const int w = t >> 5, l = t & 31;
        const int mr  = (w >> 2) * 16;
        const int nc_ = (w & 3) * 16;
        const int g   = l >> 2, tig = l & 3;
        const int lk8 = sg * 8;

        const float* xp  = xrow + lk8;
        const float* Wp0 = W + (size_t)(c0 + lr) * 1024 + lk8;
        const float* Wp1 = W + (size_t)(c0 + 32 + lr) * 1024 + lk8;
        const float* lp  = lnw + lk8;

        float4 px0 = *(const float4*)xp,  px1 = *(const float4*)(xp + 4);
        float4 pl0 = *(const float4*)lp,  pl1 = *(const float4*)(lp + 4);
        float4 pw0 = *(const float4*)Wp0, pw1 = *(const float4*)(Wp0 + 4);
        float4 pw2 = *(const float4*)Wp1, pw3 = *(const float4*)(Wp1 + 4);

        float acc[2][4] = {{0,0,0,0},{0,0,0,0}};

        for (int k0 = 0; k0 < 1024; k0 += 64) {
            __syncthreads();
            {
                float4 a0, a1;
                a0.x = (px0.x - mm) * rs * pl0.x; a0.y = (px0.y - mm) * rs * pl0.y;
                a0.z = (px0.z - mm) * rs * pl0.z; a0.w = (px0.w - mm) * rs * pl0.w;
                a1.x = (px1.x - mm) * rs * pl1.x; a1.y = (px1.y - mm) * rs * pl1.y;
                a1.z = (px1.z - mm) * rs * pl1.z; a1.w = (px1.w - mm) * rs * pl1.w;
                *(float4*)&As[lr][lk8]     = a0;
                *(float4*)&As[lr][lk8 + 4] = a1;
                *(float4*)&Ws[lr][lk8]          = pw0; *(float4*)&Ws[lr][lk8 + 4]      = pw1;
                *(float4*)&Ws[lr + 32][lk8]     = pw2; *(float4*)&Ws[lr + 32][lk8 + 4] = pw3;
            }
            __syncthreads();
            if (k0 + 64 < 1024) {
                px0 = *(const float4*)(xp  + k0 + 64); px1 = *(const float4*)(xp  + k0 + 68);
                pl0 = *(const float4*)(lp  + k0 + 64); pl1 = *(const float4*)(lp  + k0 + 68);
                pw0 = *(const float4*)(Wp0 + k0 + 64); pw1 = *(const float4*)(Wp0 + k0 + 68);
                pw2 = *(const float4*)(Wp1 + k0 + 64); pw3 = *(const float4*)(Wp1 + k0 + 68);
            }
            #pragma unroll
            for (int ks = 0; ks < 8; ks++) {
                const int kb = ks * 8;
                unsigned a0 = f2tf(As[mr + g][kb + tig]);
                unsigned a1 = f2tf(As[mr + g + 8][kb + tig]);
                unsigned a2 = f2tf(As[mr + g][kb + tig + 4]);
                unsigned a3 = f2tf(As[mr + g + 8][kb + tig + 4]);
                #pragma unroll
                for (int j = 0; j < 2; j++) {
                    unsigned b0 = f2tf(Ws[nc_ + j * 8 + g][kb + tig]);
                    unsigned b1 = f2tf(Ws[nc_ + j * 8 + g][kb + tig + 4]);
                    mma_tf32(acc[j], a0, a1, a2, a3, b0, b1);
                }
            }
        }
        const int row0 = r0 + mr + g, row1 = row0 + 8;
        #pragma unroll
        for (int j = 0; j < 2; j++) {
            const int colb = c0 + nc_ + j * 8 + 2 * tig;
            float b0v = 0.f, b1v = 0.f;
            if (bias) { b0v = bias[colb]; b1v = bias[colb + 1]; }
            OUT[(size_t)row0 * 1024 + colb]     = acc[j][0] + b0v;
            OUT[(size_t)row0 * 1024 + colb + 1] = acc[j][1] + b1v;
            OUT[(size_t)row1 * 1024 + colb]     = acc[j][2] + b0v;
            OUT[(size_t)row1 * 1024 + colb + 1] = acc[j][3] + b1v;
        }
        __threadfence();
        __syncthreads();
        if (t == 0) atomicAdd(&g_qkv_flag[rt * 16 + ct], 1);

        // ---- join the fill (work stealing; no deferred static share) ----
        fill_steal(t, sm, (float4*)out, (const float4*)ob);
        return;
    }

    // =====================================================================
    // ROLE 2: attention per (b,h) (bids 192..319). Spins on its 3 qkv flags,
    // then joins the fill.
    // =====================================================================
    if (bid < N_QKV + N_ATTN) {
        const int aidx = bid - N_QKV;
        const int b = aidx >> 4, h = aidx & 15;

        float (*w1)[65] = (float(*)[65])sm;          // wk, later wq (64x65)
        float (*w2)[65] = w1 + 64;                   // wv
        float (*kt)[65] = w2 + 64;
        float (*vt)[65] = kt + 16;
        float (*kn)[65] = vt + 16;
        float (*vi)[65] = kn + 16;
        float (*qc)[65] = vi + 16;
        float (*qn)[65] = qc + 16;
        float* rm  = (float*)(qn + 16);
        float* rr  = rm + 16;
        float* red = rr + 16;

        const int w = t >> 5, lane = t & 31;

        // stage wk->w1, wv->w2 while (possibly) waiting on producers
        {
            const int rw = t >> 4, col = (t & 15) * 4;
            #pragma unroll
            for (int p = 0; p < 4; p++) {
                int row = p * 16 + rw;
                float4 c = *(const float4*)(lkw + row * 64 + col);
                w1[row][col] = c.x; w1[row][col+1] = c.y; w1[row][col+2] = c.z; w1[row][col+3] = c.w;
                float4 e = *(const float4*)(lvw + row * 64 + col);
                w2[row][col] = e.x; w2[row][col+1] = e.y; w2[row][col+2] = e.z; w2[row][col+3] = e.w;
            }
        }
        if (t == 0) {
            while (*(volatile int*)&g_qkv_flag[(b >> 1) * 16 + h] < 3) __nanosleep(64);
            __threadfence();
        }
        __syncthreads();

        const int d = t & 63, s0 = t >> 6;
        const size_t base = (size_t)(b * 16) * 1024 + h * 64;
        #pragma unroll
        for (int r = 0; r < 4; r++) {
            int s = s0 + 4 * r;
            qc[s][d] = g_q[base + (size_t)s * 1024 + d];
            kt[s][d] = g_k[base + (size_t)s * 1024 + d];
            vt[s][d] = g_v[base + (size_t)s * 1024 + d];
        }
        __syncthreads();

        // kn_pre = k @ lkw.T + lkb, vi = v @ lvw.T + lvb
        {
            float akn[4], avi[4];
            const float bk = lkb[d], bv = lvb[d];
            #pragma unroll
            for (int r = 0; r < 4; r++) { akn[r] = bk; avi[r] = bv; }
            for (int e = 0; e < 64; e++) {
                float wke = w1[d][e], wve = w2[d][e];
                #pragma unroll
                for (int r = 0; r < 4; r++) {
                    int s = s0 + 4 * r;
                    akn[r] += kt[s][e] * wke;
                    avi[r] += vt[s][e] * wve;
                }
            }
            #pragma unroll
            for (int r = 0; r < 4; r++) { int s = s0 + 4 * r; kn[s][d] = akn[r]; vi[s][d] = avi[r]; }
        }
        __syncthreads();
        {   // LN over 64-dim kn rows
            const int s = t >> 4, l16 = t & 15;
            float v0 = kn[s][l16], v1 = kn[s][l16+16], v2 = kn[s][l16+32], v3 = kn[s][l16+48];
            float sum = v0+v1+v2+v3, sq = v0*v0+v1*v1+v2*v2+v3*v3;
            #pragma unroll
            for (int o = 8; o; o >>= 1) {
                sum += __shfl_xor_sync(0xffffffffu, sum, o);
                sq  += __shfl_xor_sync(0xffffffffu, sq,  o);
            }
            if (l16 == 0) {
                float m = sum * (1.f/64.f), var = sq * (1.f/64.f) - m*m;
                rm[s] = m; rr[s] = rsqrtf(var + 1e-5f);
            }
        }
        __syncthreads();
        {
            const float lndd = lnd[d];
            #pragma unroll
            for (int r = 0; r < 4; r++) {
                int s = s0 + 4 * r;
                kn[s][d] = (kn[s][d] - rm[s]) * rr[s] * lndd;
            }
        }
        __syncthreads();
        // restage wq into w1 (wk no longer needed)
        {
            const int rw = t >> 4, col = (t & 15) * 4;
            #pragma unroll
            for (int p = 0; p < 4; p++) {
                int row = p * 16 + rw;
                float4 a = *(const float4*)(lqw + row * 64 + col);
                w1[row][col] = a.x; w1[row][col+1] = a.y; w1[row][col+2] = a.z; w1[row][col+3] = a.w;
            }
        }
        __syncthreads();

        // ---- sync-free iteration loop: warp w owns rows sA=2w, sB=2w+1 ----
        const int d0 = lane, d1 = lane + 32;
        const int sA = 2 * w, sB = sA + 1;
        const float lqb0 = lqb[d0], lqb1 = lqb[d1];
        const float lnc0 = lnc[d0], lnc1 = lnc[d1];
        const size_t baseA = base + (size_t)sA * 1024;
        const size_t baseB = base + (size_t)sB * 1024;

        float diffacc = 0.f;
        float ipA0 = 0.f, ipA1 = 0.f, ipB0 = 0.f, ipB1 = 0.f;

        #pragma unroll
        for (int it = 0; it < 3; it++) {
            float aA0 = lqb0, aA1 = lqb1, aB0 = lqb0, aB1 = lqb1;
            #pragma unroll 16
            for (int e = 0; e < 64; e++) {
                float ca = qc[sA][e], cb = qc[sB][e];
                float w0 = w1[d0][e], wv1 = w1[d1][e];
                aA0 += ca * w0; aA1 += ca * wv1;
                aB0 += cb * w0; aB1 += cb * wv1;
            }
            float sumA = aA0 + aA1, sqA = aA0*aA0 + aA1*aA1;
            float sumB = aB0 + aB1, sqB = aB0*aB0 + aB1*aB1;
            #pragma unroll
            for (int o = 16; o; o >>= 1) {
                sumA += __shfl_xor_sync(0xffffffffu, sumA, o);
                sqA  += __shfl_xor_sync(0xffffffffu, sqA,  o);
                sumB += __shfl_xor_sync(0xffffffffu, sumB, o);
                sqB  += __shfl_xor_sync(0xffffffffu, sqB,  o);
            }
            float mA = sumA * (1.f/64.f), rA = rsqrtf(sqA * (1.f/64.f) - mA*mA + 1e-5f);
            float mB = sumB * (1.f/64.f), rB = rsqrtf(sqB * (1.f/64.f) - mB*mB + 1e-5f);
            qn[sA][d0] = (aA0 - mA) * rA * lnc0; qn[sA][d1] = (aA1 - mA) * rA * lnc1;
            qn[sB][d0] = (aB0 - mB) * rB * lnc0; qn[sB][d1] = (aB1 - mB) * rB * lnc1;
            __syncwarp();

            const int srow = (lane < 16) ? sA : sB;
            const int u = lane & 15;
            float lg = 0.f;
            #pragma unroll 16
            for (int e = 0; e < 64; e++) lg += qn[srow][e] * kn[u][e];
            lg *= 0.125f;
            float mx = lg;
            #pragma unroll
            for (int o = 8; o; o >>= 1) mx = fmaxf(mx, __shfl_xor_sync(0xffffffffu, mx, o));
            float ex = expf(lg - mx);
            float se = ex;
            #pragma unroll
            for (int o = 8; o; o >>= 1) se += __shfl_xor_sync(0xffffffffu, se, o);
            float p = ex / se;

            float oA0 = 0.f, oA1 = 0.f, oB0 = 0.f, oB1 = 0.f;
            #pragma unroll
            for (int uu = 0; uu < 16; uu++) {
                float pA = __shfl_sync(0xffffffffu, p, uu);
                float pB = __shfl_sync(0xffffffffu, p, uu + 16);
                float v0 = vi[uu][d0], vvv = vi[uu][d1];
                oA0 += pA * v0; oA1 += pA * vvv;
                oB0 += pB * v0; oB1 += pB * vvv;
            }

            if (it == 0) {
                ipA0 = oA0; ipA1 = oA1; ipB0 = oB0; ipB1 = oB1;
                qc[sA][d0] += oA0; qc[sA][d1] += oA1;
                qc[sB][d0] += oB0; qc[sB][d1] += oB1;
            } else if (it == 1) {
                diffacc += fabsf(oA0 - ipA0) + fabsf(oA1 - ipA1)
                         + fabsf(oB0 - ipB0) + fabsf(oB1 - ipB1);
                qc[sA][d0] += oA0; qc[sA][d1] += oA1;
                qc[sB][d0] += oB0; qc[sB][d1] += oB1;
                g_A1[baseA + d0] = oA0; g_A1[baseA + d1] = oA1;
                g_A1[baseB + d0] = oB0; g_A1[baseB + d1] = oB1;
            } else {
                g_A2[baseA + d0] = oA0; g_A2[baseA + d1] = oA1;
                g_A2[baseB + d0] = oB0; g_A2[baseB + d1] = oB1;
            }
            __syncwarp();
        }

        // block reduce diff -> g_diffpart[aidx], then release attn_done
        #pragma unroll
        for (int o = 16; o; o >>= 1) diffacc += __shfl_xor_sync(0xffffffffu, diffacc, o);
        if (lane == 0) red[w] = diffacc;
        __syncthreads();
        if (t == 0) {
            float v = 0.f;
            #pragma unroll
            for (int i = 0; i < 8; i++) v += red[i];
            g_diffpart[aidx] = v;
        }
        __threadfence();
        __syncthreads();
        if (t == 0) atomicAdd(&g_attn_done, 1);

        // ---- join the fill ----
        fill_steal(t, sm, (float4*)out, (const float4*)ob);
        return;
    }

    // =====================================================================
    // ROLE 3: output projection (bids 320..383). Spins until all attn done,
    // reduces diffpart deterministically, full-K tf32 GEMM, writes acc+ob.
    // Also self-resets the dependency flags for the next graph replay.
    // =====================================================================
    if (bid < N_QKV + N_ATTN + N_PROJ) {
        const int pidx = bid - (N_QKV + N_ATTN);
        const int r0 = (pidx >> 4) * 32;
        const int c0 = (pidx & 15) * 64;

        if (t == 0) {
            while (*(volatile int*)&g_attn_done < 128) __nanosleep(128);
            __threadfence();
            // self-reset: safe, all attn blocks are done; attn_done cleared by
            // the LAST proj block to pass this wait.
            g_qkv_flag[pidx] = 0;
            int p = atomicAdd(&g_proj_passed, 1);
            if (p == N_PROJ - 1) { g_attn_done = 0; g_proj_passed = 0; }
        }
        __syncthreads();

        // deterministic diff reduction (identical order in every block)
        if (t < 32) {
            float v = 0.f;
            #pragma unroll
            for (int j = 0; j < 4; j++) v += g_diffpart[t + j * 32];
            #pragma unroll
            for (int o = 16; o; o >>= 1) v += __shfl_xor_sync(0xffffffffu, v, o);
            if (t == 0) sm[0] = v;
        }
        __syncthreads();
        const float total = sm[0];
        __syncthreads();
        const float diff = total * (1.0f / 33554432.0f);
        const float* IN = (diff < (0.01f + 0.1f * diff)) ? g_A1 : g_A2;

        float (*As)[68] = (float(*)[68])sm;
        float (*Ws)[68] = As + 32;

        const int w = t >> 5, l = t & 31;
        const int mr  = (w >> 2) * 16;
        const int nc_ = (w & 3) * 16;
        const int g   = l >> 2, tig = l & 3;
        const int lr  = t >> 3, lk8 = (t & 7) * 8;

        float acc[2][4] = {{0,0,0,0},{0,0,0,0}};

        const float* Ap  = IN + (size_t)(r0 + lr) * 1024 + lk8;
        const float* Wp0 = ow + (size_t)(c0 + lr) * 1024 + lk8;
        const float* Wp1 = ow + (size_t)(c0 + 32 + lr) * 1024 + lk8;
        float4 pa0 = *(const float4*)Ap,  pa1 = *(const float4*)(Ap + 4);
        float4 pw0 = *(const float4*)Wp0, pw1 = *(const float4*)(Wp0 + 4);
        float4 pw2 = *(const float4*)Wp1, pw3 = *(const float4*)(Wp1 + 4);

        for (int k0 = 0; k0 < 1024; k0 += 64) {
            __syncthreads();
            *(float4*)&As[lr][lk8]          = pa0; *(float4*)&As[lr][lk8 + 4]      = pa1;
            *(float4*)&Ws[lr][lk8]          = pw0; *(float4*)&Ws[lr][lk8 + 4]      = pw1;
            *(float4*)&Ws[lr + 32][lk8]     = pw2; *(float4*)&Ws[lr + 32][lk8 + 4] = pw3;
            __syncthreads();
            if (k0 + 64 < 1024) {
                pa0 = *(const float4*)(Ap  + k0 + 64); pa1 = *(const float4*)(Ap  + k0 + 68);
                pw0 = *(const float4*)(Wp0 + k0 + 64); pw1 = *(const float4*)(Wp0 + k0 + 68);
                pw2 = *(const float4*)(Wp1 + k0 + 64); pw3 = *(const float4*)(Wp1 + k0 + 68);
            }
            #pragma unroll
            for (int ks = 0; ks < 8; ks++) {
                const int kb = ks * 8;
                unsigned a0 = f2tf(As[mr + g][kb + tig]);
                unsigned a1 = f2tf(As[mr + g + 8][kb + tig]);
                unsigned a2 = f2tf(As[mr + g][kb + tig + 4]);
                unsigned a3 = f2tf(As[mr + g + 8][kb + tig + 4]);
                #pragma unroll
                for (int j = 0; j < 2; j++) {
                    unsigned b0 = f2tf(Ws[nc_ + j * 8 + g][kb + tig]);
                    unsigned b1 = f2tf(Ws[nc_ + j * 8 + g][kb + tig + 4]);
                    mma_tf32(acc[j], a0, a1, a2, a3, b0, b1);
                }
            }
        }
        const int row0 = r0 + mr + g, row1 = row0 + 8;
        const size_t o0 = ((size_t)(row0 >> 4) * CTXL + (row0 & 15)) * 1024;
        const size_t o1 = ((size_t)(row1 >> 4) * CTXL + (row1 & 15)) * 1024;
        #pragma unroll
        for (int j = 0; j < 2; j++) {
            const int colb = c0 + nc_ + j * 8 + 2 * tig;
            const float b0v = ob[colb], b1v = ob[colb + 1];
            out[o0 + colb]     = acc[j][0] + b0v;
            out[o0 + colb + 1] = acc[j][1] + b1v;
            out[o1 + colb]     = acc[j][2] + b0v;
            out[o1 + colb + 1] = acc[j][3] + b1v;
        }
        return;
    }

    // =====================================================================
    // ROLE 4: dedicated fill workers (bids 384..443), stealing from t=0.
    // =====================================================================
    fill_steal(t, sm, (float4*)out, (const float4*)ob);
}

// ---------------------------------------------------------------------------
extern "C" void kernel_launch(void* const* d_in, const int* in_sizes, int n_in,
                              void* d_out, int out_size) {
    const float* x   = (const float*)d_in[0];
    const float* qw  = (const float*)d_in[1];
    const float* qb  = (const float*)d_in[2];
    const float* kw  = (const float*)d_in[3];
    const float* vw  = (const float*)d_in[4];
    const float* vb  = (const float*)d_in[5];
    const float* ow  = (const float*)d_in[6];
    const float* ob  = (const float*)d_in[7];
    const float* lna = (const float*)d_in[8];
    const float* lnb = (const float*)d_in[9];
    const float* lnc = (const float*)d_in[10];
    const float* lnd = (const float*)d_in[11];
    const float* lqw = (const float*)d_in[12];
    const float* lqb = (const float*)d_in[13];
    const float* lkw = (const float*)d_in[14];
    const float* lkb = (const float*)d_in[15];
    const float* lvw = (const float*)d_in[16];
    const float* lvb = (const float*)d_in[17];
    float* out = (float*)d_out;

    // dynamic smem sized for the attn role: (2*64*65 + 6*16*65 + 40) floats
    const int smem = (2 * 64 * 65 + 6 * 16 * 65 + 40) * 4;   // 58400 B
    cudaFuncSetAttribute(mega_kernel, cudaFuncAttributeMaxDynamicSharedMemorySize,
                         smem);

    mega_kernel<<<GRID_TOTAL, 256, smem>>>(x, qw, qb, kw, vw, vb, ow, ob,
                                           lna, lnb, lnc, lnd,
                                           lqw, lqb, lkw, lkb, lvw, lvb, out);
}